// round 1
// baseline (speedup 1.0000x reference)
#include <cuda_runtime.h>
#include <cuda_bf16.h>
#include <math.h>

// Problem constants
#define Bsz   2
#define SEQ   2048
#define DMODEL 1024
#define NH    16
#define HD    64
#define ROWS  (Bsz*SEQ)          // 4096
#define SCALE 0.03125f           // 1024^-0.5

// ---------------- scratch (device globals; no allocation allowed) ----------------
__device__ float g_xp[(size_t)ROWS * 3 * DMODEL];   // 4096 x 3072
__device__ float g_q [(size_t)Bsz * NH * SEQ * HD];
__device__ float g_k [(size_t)Bsz * NH * SEQ * HD];
__device__ float g_v [(size_t)Bsz * NH * SEQ * HD];
__device__ float g_y1[(size_t)ROWS * DMODEL];       // attn out + residual
__device__ float g_y2[(size_t)ROWS * DMODEL];       // after out proj

// ---------------- tiled SGEMM: C = A(MxK) * B(KxN) + bias ----------------
#define BM 128
#define BN 128
#define BK 16
#define APAD 4

__global__ __launch_bounds__(256)
void sgemm_bias(const float* __restrict__ A, const float* __restrict__ B,
                const float* __restrict__ bias, float* __restrict__ C,
                int M, int N, int K)
{
    __shared__ float As[BK][BM + APAD];  // transposed A tile
    __shared__ float Bs[BK][BN];

    const int tid = threadIdx.x;
    const int bm = blockIdx.y * BM;
    const int bn = blockIdx.x * BN;

    const int a_row  = tid >> 2;          // 0..63
    const int a_col4 = tid & 3;           // 0..3 (float4 within BK=16)
    const int b_row  = tid >> 5;          // 0..7
    const int b_col4 = tid & 31;          // 0..31

    const int tx = tid & 15;
    const int ty = tid >> 4;

    float acc[8][8];
    #pragma unroll
    for (int i = 0; i < 8; i++)
        #pragma unroll
        for (int j = 0; j < 8; j++) acc[i][j] = 0.f;

    for (int k0 = 0; k0 < K; k0 += BK) {
        // load A tile (BM x BK), store transposed
        #pragma unroll
        for (int p = 0; p < 2; p++) {
            int r = a_row + p * 64;
            float4 va = *(const float4*)&A[(size_t)(bm + r) * K + k0 + a_col4 * 4];
            As[a_col4 * 4 + 0][r] = va.x;
            As[a_col4 * 4 + 1][r] = va.y;
            As[a_col4 * 4 + 2][r] = va.z;
            As[a_col4 * 4 + 3][r] = va.w;
        }
        // load B tile (BK x BN)
        #pragma unroll
        for (int p = 0; p < 2; p++) {
            int r = b_row + p * 8;
            *(float4*)&Bs[r][b_col4 * 4] =
                *(const float4*)&B[(size_t)(k0 + r) * N + bn + b_col4 * 4];
        }
        __syncthreads();

        #pragma unroll
        for (int kk = 0; kk < BK; kk++) {
            float ra[8], rb[8];
            #pragma unroll
            for (int i = 0; i < 8; i++) ra[i] = As[kk][ty * 8 + i];
            #pragma unroll
            for (int j = 0; j < 8; j++) rb[j] = Bs[kk][tx * 8 + j];
            #pragma unroll
            for (int i = 0; i < 8; i++)
                #pragma unroll
                for (int j = 0; j < 8; j++)
                    acc[i][j] += ra[i] * rb[j];
        }
        __syncthreads();
    }

    const float4 bia0 = *(const float4*)&bias[bn + tx * 8];
    const float4 bia1 = *(const float4*)&bias[bn + tx * 8 + 4];
    #pragma unroll
    for (int i = 0; i < 8; i++) {
        size_t m = (size_t)(bm + ty * 8 + i);
        float4 o0, o1;
        o0.x = acc[i][0] + bia0.x; o0.y = acc[i][1] + bia0.y;
        o0.z = acc[i][2] + bia0.z; o0.w = acc[i][3] + bia0.w;
        o1.x = acc[i][4] + bia1.x; o1.y = acc[i][5] + bia1.y;
        o1.z = acc[i][6] + bia1.z; o1.w = acc[i][7] + bia1.w;
        *(float4*)&C[m * N + bn + tx * 8]     = o0;
        *(float4*)&C[m * N + bn + tx * 8 + 4] = o1;
    }
}

// ---------------- split QKV + RoPE + head transpose ----------------
// xp: [ROWS][3*DMODEL]; outputs Q/K/V: [B*H][S][HD]
__global__ __launch_bounds__(256)
void split_rope(const float* __restrict__ xp,
                float* __restrict__ Q, float* __restrict__ K, float* __restrict__ V)
{
    int idx = blockIdx.x * 256 + threadIdx.x;        // over ROWS*DMODEL
    int col = idx & (DMODEL - 1);
    int bs  = idx >> 10;
    int h = col >> 6;
    int d = col & (HD - 1);
    int s = bs & (SEQ - 1);
    int b = bs >> 11;

    const float* base = xp + (size_t)bs * (3 * DMODEL);
    float qv, kv;
    if (d < 32) {
        int i = d >> 1;
        double ang = (double)s * pow(10000.0, -(double)(2 * i) / 32.0);
        double cd, sd;
        sincos(ang, &sd, &cd);
        float c = (float)cd, sn = (float)sd;
        float q0 = base[col],          q1 = base[col ^ 1];
        float k0 = base[DMODEL + col], k1 = base[DMODEL + (col ^ 1)];
        if (d & 1) { qv = q0 * c + q1 * sn; kv = k0 * c + k1 * sn; }
        else       { qv = q0 * c - q1 * sn; kv = k0 * c - k1 * sn; }
    } else {
        qv = base[col];
        kv = base[DMODEL + col];
    }
    float vv = base[2 * DMODEL + col];

    size_t o = (((size_t)(b * NH + h)) * SEQ + s) * HD + d;
    Q[o] = qv; K[o] = kv; V[o] = vv;
}

// ---------------- flash attention (fp32), 1 thread = 1 query ----------------
// grid: (SEQ/128, B*NH), block 128.  Writes y1 = attn_out + residual x.
#define BCK 32
__global__ __launch_bounds__(128)
void attn_kernel(const float* __restrict__ Q, const float* __restrict__ K,
                 const float* __restrict__ V, const float* __restrict__ x,
                 float* __restrict__ y1)
{
    __shared__ float Ks[BCK][HD];
    __shared__ float Vs[BCK][HD];

    const int bh = blockIdx.y;
    const int q0 = blockIdx.x * 128;
    const int t  = threadIdx.x;

    const float* Qb = Q + (size_t)bh * SEQ * HD;
    const float* Kb = K + (size_t)bh * SEQ * HD;
    const float* Vb = V + (size_t)bh * SEQ * HD;

    // load my query row into registers
    float q[HD];
    {
        const float* qr = Qb + (size_t)(q0 + t) * HD;
        #pragma unroll
        for (int d4 = 0; d4 < 16; d4++) {
            float4 v4 = *(const float4*)&qr[d4 * 4];
            q[d4 * 4 + 0] = v4.x; q[d4 * 4 + 1] = v4.y;
            q[d4 * 4 + 2] = v4.z; q[d4 * 4 + 3] = v4.w;
        }
    }

    float acc[HD];
    #pragma unroll
    for (int d = 0; d < HD; d++) acc[d] = 0.f;
    float m = -INFINITY, l = 0.f;

    for (int kt = 0; kt < SEQ; kt += BCK) {
        __syncthreads();   // protect previous tile reads
        // cooperative load K/V tile: BCK*HD = 2048 floats = 512 float4, 128 threads -> 4 each
        #pragma unroll
        for (int p = 0; p < 4; p++) {
            int li = p * 128 + t;
            int r = li >> 4, c4 = li & 15;
            *(float4*)&Ks[r][c4 * 4] = *(const float4*)&Kb[(size_t)(kt + r) * HD + c4 * 4];
            *(float4*)&Vs[r][c4 * 4] = *(const float4*)&Vb[(size_t)(kt + r) * HD + c4 * 4];
        }
        __syncthreads();

        float sc[BCK];
        float mt = m;
        #pragma unroll
        for (int j = 0; j < BCK; j++) {
            float s = 0.f;
            #pragma unroll
            for (int d4 = 0; d4 < 16; d4++) {
                float4 k4 = *(const float4*)&Ks[j][d4 * 4];
                s += q[d4 * 4 + 0] * k4.x;
                s += q[d4 * 4 + 1] * k4.y;
                s += q[d4 * 4 + 2] * k4.z;
                s += q[d4 * 4 + 3] * k4.w;
            }
            s *= SCALE;
            sc[j] = s;
            mt = fmaxf(mt, s);
        }

        float corr = __expf(m - mt);
        m = mt;
        l *= corr;
        #pragma unroll
        for (int d = 0; d < HD; d++) acc[d] *= corr;

        #pragma unroll
        for (int j = 0; j < BCK; j++) {
            float p = __expf(sc[j] - m);
            l += p;
            #pragma unroll
            for (int d4 = 0; d4 < 16; d4++) {
                float4 v4 = *(const float4*)&Vs[j][d4 * 4];
                acc[d4 * 4 + 0] += p * v4.x;
                acc[d4 * 4 + 1] += p * v4.y;
                acc[d4 * 4 + 2] += p * v4.z;
                acc[d4 * 4 + 3] += p * v4.w;
            }
        }
    }

    // write out (head-transpose back) + residual
    const int b = bh / NH, h = bh % NH;
    const size_t row = (size_t)b * SEQ + q0 + t;
    const float* xr = x  + row * DMODEL + h * HD;
    float*       yr = y1 + row * DMODEL + h * HD;
    const float inv_l = 1.f / l;
    #pragma unroll
    for (int d4 = 0; d4 < 16; d4++) {
        float4 xv = *(const float4*)&xr[d4 * 4];
        float4 o;
        o.x = acc[d4 * 4 + 0] * inv_l + xv.x;
        o.y = acc[d4 * 4 + 1] * inv_l + xv.y;
        o.z = acc[d4 * 4 + 2] * inv_l + xv.z;
        o.w = acc[d4 * 4 + 3] * inv_l + xv.w;
        *(float4*)&yr[d4 * 4] = o;
    }
}

// ---------------- LayerNorm ----------------
__inline__ __device__ float warpsum(float v) {
    #pragma unroll
    for (int o = 16; o; o >>= 1) v += __shfl_xor_sync(0xffffffffu, v, o);
    return v;
}

__global__ __launch_bounds__(256)
void ln_kernel(const float* __restrict__ Y, const float* __restrict__ gamma,
               const float* __restrict__ beta, float* __restrict__ out)
{
    const int row = blockIdx.x;
    const int t = threadIdx.x;
    const float* yr = Y + (size_t)row * DMODEL;

    float vals[4];
    float s = 0.f, s2 = 0.f;
    #pragma unroll
    for (int k = 0; k < 4; k++) {
        float v = yr[t + k * 256];
        vals[k] = v;
        s += v; s2 += v * v;
    }
    s = warpsum(s); s2 = warpsum(s2);

    __shared__ float sh[16];
    int w = t >> 5, ln = t & 31;
    if (ln == 0) { sh[w] = s; sh[8 + w] = s2; }
    __syncthreads();
    if (t == 0) {
        float a = 0.f, a2 = 0.f;
        #pragma unroll
        for (int i = 0; i < 8; i++) { a += sh[i]; a2 += sh[8 + i]; }
        sh[0] = a; sh[8] = a2;
    }
    __syncthreads();
    const float mu  = sh[0] * (1.f / DMODEL);
    const float var = sh[8] * (1.f / DMODEL) - mu * mu;
    const float inv = rsqrtf(var + 1e-5f);

    #pragma unroll
    for (int k = 0; k < 4; k++) {
        int c = t + k * 256;
        out[(size_t)row * DMODEL + c] = (vals[k] - mu) * inv * gamma[c] + beta[c];
    }
}

// ---------------- launch ----------------
extern "C" void kernel_launch(void* const* d_in, const int* in_sizes, int n_in,
                              void* d_out, int out_size)
{
    const float* x      = (const float*)d_in[0];
    const float* w_qkv  = (const float*)d_in[1];
    const float* b_qkv  = (const float*)d_in[2];
    const float* w_out  = (const float*)d_in[3];
    const float* b_out  = (const float*)d_in[4];
    const float* gammap = (const float*)d_in[5];
    const float* betap  = (const float*)d_in[6];
    float* out = (float*)d_out;

    float *xp, *Q, *K, *V, *y1, *y2;
    cudaGetSymbolAddress((void**)&xp, g_xp);
    cudaGetSymbolAddress((void**)&Q,  g_q);
    cudaGetSymbolAddress((void**)&K,  g_k);
    cudaGetSymbolAddress((void**)&V,  g_v);
    cudaGetSymbolAddress((void**)&y1, g_y1);
    cudaGetSymbolAddress((void**)&y2, g_y2);

    // 1. QKV projection: (4096x1024) @ (1024x3072)
    dim3 g1(3 * DMODEL / BN, ROWS / BM);
    sgemm_bias<<<g1, 256>>>(x, w_qkv, b_qkv, xp, ROWS, 3 * DMODEL, DMODEL);

    // 2. split + RoPE + transpose to [B*H][S][HD]
    split_rope<<<(ROWS * DMODEL) / 256, 256>>>(xp, Q, K, V);

    // 3. attention + residual
    dim3 ga(SEQ / 128, Bsz * NH);
    attn_kernel<<<ga, 128>>>(Q, K, V, x, y1);

    // 4. output projection: (4096x1024) @ (1024x1024)
    dim3 g2(DMODEL / BN, ROWS / BM);
    sgemm_bias<<<g2, 256>>>(y1, w_out, b_out, y2, ROWS, DMODEL, DMODEL);

    // 5. layernorm
    ln_kernel<<<ROWS, 256>>>(y2, gammap, betap, out);
}

// round 3
// speedup vs baseline: 1.2228x; 1.2228x over previous
#include <cuda_runtime.h>
#include <cuda_bf16.h>
#include <math.h>
#include <stdint.h>

// Problem constants
#define Bsz   2
#define SEQ   2048
#define DMODEL 1024
#define NH    16
#define HD    64
#define ROWS  (Bsz*SEQ)          // 4096
#define SCALE 0.03125f           // 1024^-0.5
#define LOG2E 1.4426950408889634f

// ---------------- scratch (device globals; no allocation allowed) ----------------
__device__ float g_xp[(size_t)ROWS * 3 * DMODEL];
__device__ float g_q [(size_t)Bsz * NH * SEQ * HD];
__device__ float g_k [(size_t)Bsz * NH * SEQ * HD];
__device__ float g_v [(size_t)Bsz * NH * SEQ * HD];
__device__ float g_y1[(size_t)ROWS * DMODEL];
__device__ float g_y2[(size_t)ROWS * DMODEL];

// ---------------- cp.async helpers ----------------
__device__ __forceinline__ void cp_async16(unsigned int dst_smem, const void* src) {
    asm volatile("cp.async.cg.shared.global [%0], [%1], 16;\n" :: "r"(dst_smem), "l"(src));
}
__device__ __forceinline__ void cp_commit() {
    asm volatile("cp.async.commit_group;\n");
}
template<int N>
__device__ __forceinline__ void cp_wait() {
    asm volatile("cp.async.wait_group %0;\n" :: "n"(N));
}

// ---------------- tiled SGEMM with 2-stage double buffering ----------------
#define BM 128
#define BN 128
#define BK 16
#define APAD 4

__global__ __launch_bounds__(256, 2)
void sgemm_bias(const float* __restrict__ A, const float* __restrict__ B,
                const float* __restrict__ bias, float* __restrict__ C,
                int M, int N, int K)
{
    __shared__ float As[2][BK][BM + APAD];
    __shared__ float Bs[2][BK][BN];

    const int tid = threadIdx.x;
    const int bm = blockIdx.y * BM;
    const int bn = blockIdx.x * BN;

    const int a_row  = tid >> 2;          // 0..63
    const int a_col4 = tid & 3;           // 0..3
    const int b_row  = tid >> 5;          // 0..7
    const int b_col4 = tid & 31;          // 0..31

    const int tx = tid & 15;
    const int ty = tid >> 4;

    float acc[8][8];
    #pragma unroll
    for (int i = 0; i < 8; i++)
        #pragma unroll
        for (int j = 0; j < 8; j++) acc[i][j] = 0.f;

    float4 va[2], vb[2];

    // global load into registers for k0
    auto gload = [&](int k0) {
        #pragma unroll
        for (int p = 0; p < 2; p++) {
            va[p] = *(const float4*)&A[(size_t)(bm + a_row + p * 64) * K + k0 + a_col4 * 4];
            vb[p] = *(const float4*)&B[(size_t)(k0 + b_row + p * 8) * N + bn + b_col4 * 4];
        }
    };
    // store staged registers into smem stage s
    auto sstore = [&](int s) {
        #pragma unroll
        for (int p = 0; p < 2; p++) {
            int r = a_row + p * 64;
            As[s][a_col4 * 4 + 0][r] = va[p].x;
            As[s][a_col4 * 4 + 1][r] = va[p].y;
            As[s][a_col4 * 4 + 2][r] = va[p].z;
            As[s][a_col4 * 4 + 3][r] = va[p].w;
            *(float4*)&Bs[s][b_row + p * 8][b_col4 * 4] = vb[p];
        }
    };
    auto compute = [&](int s) {
        #pragma unroll
        for (int kk = 0; kk < BK; kk++) {
            float ra[8], rb[8];
            #pragma unroll
            for (int i = 0; i < 8; i++) ra[i] = As[s][kk][ty * 8 + i];
            #pragma unroll
            for (int j = 0; j < 8; j++) rb[j] = Bs[s][kk][tx * 8 + j];
            #pragma unroll
            for (int i = 0; i < 8; i++)
                #pragma unroll
                for (int j = 0; j < 8; j++)
                    acc[i][j] += ra[i] * rb[j];
        }
    };

    gload(0);
    sstore(0);
    __syncthreads();

    int buf = 0;
    for (int k0 = BK; ; k0 += BK) {
        bool more = (k0 < K);
        if (more) gload(k0);
        compute(buf);
        if (!more) break;
        sstore(buf ^ 1);
        __syncthreads();
        buf ^= 1;
    }

    const float4 bia0 = *(const float4*)&bias[bn + tx * 8];
    const float4 bia1 = *(const float4*)&bias[bn + tx * 8 + 4];
    #pragma unroll
    for (int i = 0; i < 8; i++) {
        size_t m = (size_t)(bm + ty * 8 + i);
        float4 o0, o1;
        o0.x = acc[i][0] + bia0.x; o0.y = acc[i][1] + bia0.y;
        o0.z = acc[i][2] + bia0.z; o0.w = acc[i][3] + bia0.w;
        o1.x = acc[i][4] + bia1.x; o1.y = acc[i][5] + bia1.y;
        o1.z = acc[i][6] + bia1.z; o1.w = acc[i][7] + bia1.w;
        *(float4*)&C[m * N + bn + tx * 8]     = o0;
        *(float4*)&C[m * N + bn + tx * 8 + 4] = o1;
    }
}

// ---------------- split QKV + RoPE (fp32) + head transpose ----------------
__global__ __launch_bounds__(256)
void split_rope(const float* __restrict__ xp,
                float* __restrict__ Q, float* __restrict__ K, float* __restrict__ V)
{
    int idx = blockIdx.x * 256 + threadIdx.x;
    int col = idx & (DMODEL - 1);
    int bs  = idx >> 10;
    int h = col >> 6;
    int d = col & (HD - 1);
    int s = bs & (SEQ - 1);
    int b = bs >> 11;

    const float* base = xp + (size_t)bs * (3 * DMODEL);
    float qv, kv;
    if (d < 32) {
        int i = d >> 1;
        // inv_freq = 10000^(-(2i)/32) in fp32
        float invf = exp2f(-13.287712379549449f * ((float)(2 * i) * (1.0f / 32.0f)));
        float ang = (float)s * invf;
        float sn, c;
        sincosf(ang, &sn, &c);
        float q0 = base[col],          q1 = base[col ^ 1];
        float k0 = base[DMODEL + col], k1 = base[DMODEL + (col ^ 1)];
        if (d & 1) { qv = q0 * c + q1 * sn; kv = k0 * c + k1 * sn; }
        else       { qv = q0 * c - q1 * sn; kv = k0 * c - k1 * sn; }
    } else {
        qv = base[col];
        kv = base[DMODEL + col];
    }
    float vv = base[2 * DMODEL + col];

    size_t o = (((size_t)(b * NH + h)) * SEQ + s) * HD + d;
    Q[o] = qv; K[o] = kv; V[o] = vv;
}

// ---------------- flash attention (fp32), cp.async double-buffered K/V ----------------
#define BCK 32
__global__ __launch_bounds__(128)
void attn_kernel(const float* __restrict__ Q, const float* __restrict__ K,
                 const float* __restrict__ V, const float* __restrict__ x,
                 float* __restrict__ y1)
{
    __shared__ float Ks[2][BCK][HD];
    __shared__ float Vs[2][BCK][HD];

    const int bh = blockIdx.y;
    const int q0 = blockIdx.x * 128;
    const int t  = threadIdx.x;

    const float* Qb = Q + (size_t)bh * SEQ * HD;
    const float* Kb = K + (size_t)bh * SEQ * HD;
    const float* Vb = V + (size_t)bh * SEQ * HD;

    // prefetch helper: tile starting at key kt into stage s
    const int pr_r  = t >> 4;       // 0..7
    const int pr_c4 = t & 15;       // 0..15
    auto prefetch = [&](int kt, int s) {
        #pragma unroll
        for (int p = 0; p < 4; p++) {
            int r = pr_r + p * 8;
            unsigned int dk = (unsigned int)__cvta_generic_to_shared(&Ks[s][r][pr_c4 * 4]);
            unsigned int dv = (unsigned int)__cvta_generic_to_shared(&Vs[s][r][pr_c4 * 4]);
            cp_async16(dk, &Kb[(size_t)(kt + r) * HD + pr_c4 * 4]);
            cp_async16(dv, &Vb[(size_t)(kt + r) * HD + pr_c4 * 4]);
        }
    };

    // load my query row into registers (scaled into log2 domain)
    float q[HD];
    {
        const float* qr = Qb + (size_t)(q0 + t) * HD;
        #pragma unroll
        for (int d4 = 0; d4 < 16; d4++) {
            float4 v4 = *(const float4*)&qr[d4 * 4];
            q[d4 * 4 + 0] = v4.x * (SCALE * LOG2E);
            q[d4 * 4 + 1] = v4.y * (SCALE * LOG2E);
            q[d4 * 4 + 2] = v4.z * (SCALE * LOG2E);
            q[d4 * 4 + 3] = v4.w * (SCALE * LOG2E);
        }
    }

    float acc[HD];
    #pragma unroll
    for (int d = 0; d < HD; d++) acc[d] = 0.f;
    float m = -1e30f, l = 0.f;

    prefetch(0, 0);
    cp_commit();

    int buf = 0;
    for (int kt = 0; kt < SEQ; kt += BCK) {
        if (kt + BCK < SEQ) prefetch(kt + BCK, buf ^ 1);
        cp_commit();
        cp_wait<1>();          // current tile's group complete
        __syncthreads();

        float sc[BCK];
        float mt = m;
        #pragma unroll
        for (int j = 0; j < BCK; j++) {
            float s = 0.f;
            #pragma unroll
            for (int d4 = 0; d4 < 16; d4++) {
                float4 k4 = *(const float4*)&Ks[buf][j][d4 * 4];
                s += q[d4 * 4 + 0] * k4.x;
                s += q[d4 * 4 + 1] * k4.y;
                s += q[d4 * 4 + 2] * k4.z;
                s += q[d4 * 4 + 3] * k4.w;
            }
            sc[j] = s;                 // log2-domain score
            mt = fmaxf(mt, s);
        }

        float corr = exp2f(m - mt);
        m = mt;
        l *= corr;
        #pragma unroll
        for (int d = 0; d < HD; d++) acc[d] *= corr;

        #pragma unroll
        for (int j = 0; j < BCK; j++) {
            float p = exp2f(sc[j] - m);
            l += p;
            #pragma unroll
            for (int d4 = 0; d4 < 16; d4++) {
                float4 v4 = *(const float4*)&Vs[buf][j][d4 * 4];
                acc[d4 * 4 + 0] += p * v4.x;
                acc[d4 * 4 + 1] += p * v4.y;
                acc[d4 * 4 + 2] += p * v4.z;
                acc[d4 * 4 + 3] += p * v4.w;
            }
        }

        __syncthreads();      // everyone done reading stage buf before it is refilled
        buf ^= 1;
    }

    const int b = bh / NH, h = bh % NH;
    const size_t row = (size_t)b * SEQ + q0 + t;
    const float* xr = x  + row * DMODEL + h * HD;
    float*       yr = y1 + row * DMODEL + h * HD;
    const float inv_l = 1.f / l;
    #pragma unroll
    for (int d4 = 0; d4 < 16; d4++) {
        float4 xv = *(const float4*)&xr[d4 * 4];
        float4 o;
        o.x = acc[d4 * 4 + 0] * inv_l + xv.x;
        o.y = acc[d4 * 4 + 1] * inv_l + xv.y;
        o.z = acc[d4 * 4 + 2] * inv_l + xv.z;
        o.w = acc[d4 * 4 + 3] * inv_l + xv.w;
        *(float4*)&yr[d4 * 4] = o;
    }
}

// ---------------- LayerNorm ----------------
__inline__ __device__ float warpsum(float v) {
    #pragma unroll
    for (int o = 16; o; o >>= 1) v += __shfl_xor_sync(0xffffffffu, v, o);
    return v;
}

__global__ __launch_bounds__(256)
void ln_kernel(const float* __restrict__ Y, const float* __restrict__ gamma,
               const float* __restrict__ beta, float* __restrict__ out)
{
    const int row = blockIdx.x;
    const int t = threadIdx.x;
    const float* yr = Y + (size_t)row * DMODEL;

    float vals[4];
    float s = 0.f, s2 = 0.f;
    #pragma unroll
    for (int k = 0; k < 4; k++) {
        float v = yr[t + k * 256];
        vals[k] = v;
        s += v; s2 += v * v;
    }
    s = warpsum(s); s2 = warpsum(s2);

    __shared__ float sh[16];
    int w = t >> 5, ln = t & 31;
    if (ln == 0) { sh[w] = s; sh[8 + w] = s2; }
    __syncthreads();
    if (t == 0) {
        float a = 0.f, a2 = 0.f;
        #pragma unroll
        for (int i = 0; i < 8; i++) { a += sh[i]; a2 += sh[8 + i]; }
        sh[0] = a; sh[8] = a2;
    }
    __syncthreads();
    const float mu  = sh[0] * (1.f / DMODEL);
    const float var = sh[8] * (1.f / DMODEL) - mu * mu;
    const float inv = rsqrtf(var + 1e-5f);

    #pragma unroll
    for (int k = 0; k < 4; k++) {
        int c = t + k * 256;
        out[(size_t)row * DMODEL + c] = (vals[k] - mu) * inv * gamma[c] + beta[c];
    }
}

// ---------------- launch ----------------
extern "C" void kernel_launch(void* const* d_in, const int* in_sizes, int n_in,
                              void* d_out, int out_size)
{
    const float* x      = (const float*)d_in[0];
    const float* w_qkv  = (const float*)d_in[1];
    const float* b_qkv  = (const float*)d_in[2];
    const float* w_out  = (const float*)d_in[3];
    const float* b_out  = (const float*)d_in[4];
    const float* gammap = (const float*)d_in[5];
    const float* betap  = (const float*)d_in[6];
    float* out = (float*)d_out;

    float *xp, *Q, *K, *V, *y1, *y2;
    cudaGetSymbolAddress((void**)&xp, g_xp);
    cudaGetSymbolAddress((void**)&Q,  g_q);
    cudaGetSymbolAddress((void**)&K,  g_k);
    cudaGetSymbolAddress((void**)&V,  g_v);
    cudaGetSymbolAddress((void**)&y1, g_y1);
    cudaGetSymbolAddress((void**)&y2, g_y2);

    dim3 g1(3 * DMODEL / BN, ROWS / BM);
    sgemm_bias<<<g1, 256>>>(x, w_qkv, b_qkv, xp, ROWS, 3 * DMODEL, DMODEL);

    split_rope<<<(ROWS * DMODEL) / 256, 256>>>(xp, Q, K, V);

    dim3 ga(SEQ / 128, Bsz * NH);
    attn_kernel<<<ga, 128>>>(Q, K, V, x, y1);

    dim3 g2(DMODEL / BN, ROWS / BM);
    sgemm_bias<<<g2, 256>>>(y1, w_out, b_out, y2, ROWS, DMODEL, DMODEL);

    ln_kernel<<<ROWS, 256>>>(y2, gammap, betap, out);
}

// round 5
// speedup vs baseline: 1.4838x; 1.2134x over previous
#include <cuda_runtime.h>
#include <cuda_bf16.h>
#include <math.h>
#include <stdint.h>

// Problem constants
#define Bsz   2
#define SEQ   2048
#define DMODEL 1024
#define NH    16
#define HD    64
#define ROWS  (Bsz*SEQ)          // 4096
#define SCALE 0.03125f
#define LOG2E 1.4426950408889634f

// ---------------- scratch ----------------
__device__ float g_xp[(size_t)ROWS * 3 * DMODEL];
__device__ float g_q [(size_t)Bsz * NH * SEQ * HD];
__device__ float g_k [(size_t)Bsz * NH * SEQ * HD];
__device__ float g_v [(size_t)Bsz * NH * SEQ * HD];
__device__ float g_y1[(size_t)ROWS * DMODEL];
__device__ float g_y2[(size_t)ROWS * DMODEL];
// bf16 split operands
__device__ __nv_bfloat16 g_xh [(size_t)ROWS * DMODEL];
__device__ __nv_bfloat16 g_xl [(size_t)ROWS * DMODEL];
__device__ __nv_bfloat16 g_wqh[(size_t)3 * DMODEL * DMODEL];  // [3072,1024] (N,K)
__device__ __nv_bfloat16 g_wql[(size_t)3 * DMODEL * DMODEL];
__device__ __nv_bfloat16 g_woh[(size_t)DMODEL * DMODEL];      // [1024,1024]
__device__ __nv_bfloat16 g_wol[(size_t)DMODEL * DMODEL];
__device__ __nv_bfloat16 g_y1h[(size_t)ROWS * DMODEL];
__device__ __nv_bfloat16 g_y1l[(size_t)ROWS * DMODEL];

// ---------------- helpers ----------------
__device__ __forceinline__ unsigned smem_u32(const void* p) {
    unsigned a;
    asm("{ .reg .u64 t; cvta.to.shared.u64 t, %1; cvt.u32.u64 %0, t; }" : "=r"(a) : "l"(p));
    return a;
}
__device__ __forceinline__ void cp_async16(unsigned dst, const void* src) {
    asm volatile("cp.async.cg.shared.global [%0], [%1], 16;\n" :: "r"(dst), "l"(src));
}
__device__ __forceinline__ void cp_commit() { asm volatile("cp.async.commit_group;\n"); }
template<int N> __device__ __forceinline__ void cp_wait() {
    asm volatile("cp.async.wait_group %0;\n" :: "n"(N));
}

__device__ __forceinline__ void mma_bf16(float* c, unsigned a0, unsigned a1, unsigned a2, unsigned a3,
                                         unsigned b0, unsigned b1) {
    asm volatile(
        "mma.sync.aligned.m16n8k16.row.col.f32.bf16.bf16.f32 "
        "{%0,%1,%2,%3}, {%4,%5,%6,%7}, {%8,%9}, {%0,%1,%2,%3};"
        : "+f"(c[0]), "+f"(c[1]), "+f"(c[2]), "+f"(c[3])
        : "r"(a0), "r"(a1), "r"(a2), "r"(a3), "r"(b0), "r"(b1));
}

// ---------------- HMMA split-bf16 GEMM ----------------
// C[M,N] = (Ah+Al)[M,K] * (Bh+Bl)[N,K]^T + bias   (3-pass split bf16, fp32 accum)
// CTA tile 128x128, 8 warps (4m x 2n), warp tile 32x64, BK=32.
// smem rows padded to 80B -> conflict-free fragment LDS.
#define GP 80                 // row pitch bytes (32 bf16 data + 16B pad)
#define T_A_H 0
#define T_A_L 10240
#define T_B_H 20480
#define T_B_L 30720
#define STG   40960

__global__ __launch_bounds__(256, 1)
void gemm_mma(const __nv_bfloat16* __restrict__ Ah, const __nv_bfloat16* __restrict__ Al,
              const __nv_bfloat16* __restrict__ Bh, const __nv_bfloat16* __restrict__ Bl,
              const float* __restrict__ bias, float* __restrict__ C,
              int N, int K)
{
    extern __shared__ char dsm[];
    const int tid = threadIdx.x;
    const int wid = tid >> 5;
    const int lid = tid & 31;
    const int wm = wid & 3;        // warp m index 0..3
    const int wn = wid >> 2;       // warp n index 0..1
    const int bm = blockIdx.y * 128;
    const int bn = blockIdx.x * 128;

    const int gq = lid >> 2;       // lane group 0..7
    const int gr = lid & 3;        // lane in group 0..3

    float acc[2][8][4];
    #pragma unroll
    for (int mi = 0; mi < 2; mi++)
        #pragma unroll
        for (int ni = 0; ni < 8; ni++)
            #pragma unroll
            for (int e = 0; e < 4; e++) acc[mi][ni][e] = 0.f;

    const int KITER = K / 32;

    auto prefetch = [&](int it, int s) {
        const int kt = it * 32;
        char* base = dsm + s * STG;
        #pragma unroll
        for (int p = 0; p < 2; p++) {
            int idx = p * 256 + tid;
            int r = idx >> 2, c = idx & 3;
            unsigned dst = smem_u32(base + r * GP + c * 16);
            const size_t ga = (size_t)(bm + r) * K + kt + c * 8;
            const size_t gb = (size_t)(bn + r) * K + kt + c * 8;
            cp_async16(dst + T_A_H, Ah + ga);
            cp_async16(dst + T_A_L, Al + ga);
            cp_async16(dst + T_B_H, Bh + gb);
            cp_async16(dst + T_B_L, Bl + gb);
        }
    };

    prefetch(0, 0); cp_commit();

    int buf = 0;
    for (int i = 0; i < KITER; i++) {
        if (i + 1 < KITER) prefetch(i + 1, buf ^ 1);
        cp_commit();
        cp_wait<1>();
        __syncthreads();

        const char* sA = dsm + buf * STG;
        const char* sB = sA + T_B_H;

        #pragma unroll
        for (int ks = 0; ks < 2; ks++) {
            const int kc2 = (ks * 16 + gr * 2) * 2;   // byte offset of k column pair
            unsigned aH[2][4], aL[2][4];
            #pragma unroll
            for (int mi = 0; mi < 2; mi++) {
                const int r0 = wm * 32 + mi * 16 + gq;
                const char* pH = sA + T_A_H + kc2;
                const char* pL = sA + T_A_L + kc2;
                aH[mi][0] = *(const unsigned*)(pH + r0 * GP);
                aH[mi][1] = *(const unsigned*)(pH + (r0 + 8) * GP);
                aH[mi][2] = *(const unsigned*)(pH + r0 * GP + 16);
                aH[mi][3] = *(const unsigned*)(pH + (r0 + 8) * GP + 16);
                aL[mi][0] = *(const unsigned*)(pL + r0 * GP);
                aL[mi][1] = *(const unsigned*)(pL + (r0 + 8) * GP);
                aL[mi][2] = *(const unsigned*)(pL + r0 * GP + 16);
                aL[mi][3] = *(const unsigned*)(pL + (r0 + 8) * GP + 16);
            }
            #pragma unroll
            for (int ni = 0; ni < 8; ni++) {
                const int n0 = wn * 64 + ni * 8 + gq;
                unsigned b0h = *(const unsigned*)(sB + n0 * GP + kc2);
                unsigned b1h = *(const unsigned*)(sB + n0 * GP + kc2 + 16);
                unsigned b0l = *(const unsigned*)(sB + 10240 + n0 * GP + kc2);
                unsigned b1l = *(const unsigned*)(sB + 10240 + n0 * GP + kc2 + 16);
                #pragma unroll
                for (int mi = 0; mi < 2; mi++) {
                    mma_bf16(acc[mi][ni], aH[mi][0], aH[mi][1], aH[mi][2], aH[mi][3], b0h, b1h);
                    mma_bf16(acc[mi][ni], aH[mi][0], aH[mi][1], aH[mi][2], aH[mi][3], b0l, b1l);
                    mma_bf16(acc[mi][ni], aL[mi][0], aL[mi][1], aL[mi][2], aL[mi][3], b0h, b1h);
                }
            }
        }
        __syncthreads();
        buf ^= 1;
    }

    // epilogue
    #pragma unroll
    for (int mi = 0; mi < 2; mi++) {
        const int row = bm + wm * 32 + mi * 16 + gq;
        #pragma unroll
        for (int ni = 0; ni < 8; ni++) {
            const int col = bn + wn * 64 + ni * 8 + gr * 2;
            const float2 bb = *(const float2*)&bias[col];
            float2 o0, o1;
            o0.x = acc[mi][ni][0] + bb.x; o0.y = acc[mi][ni][1] + bb.y;
            o1.x = acc[mi][ni][2] + bb.x; o1.y = acc[mi][ni][3] + bb.y;
            *(float2*)&C[(size_t)row * N + col]       = o0;
            *(float2*)&C[(size_t)(row + 8) * N + col] = o1;
        }
    }
}

// ---------------- bf16 hi/lo split of x ----------------
__global__ __launch_bounds__(256)
void split_x(const float* __restrict__ X, __nv_bfloat16* __restrict__ Xh,
             __nv_bfloat16* __restrict__ Xl)
{
    int i = blockIdx.x * 256 + threadIdx.x;
    float v = X[i];
    __nv_bfloat16 h = __float2bfloat16(v);
    Xh[i] = h;
    Xl[i] = __float2bfloat16(v - __bfloat162float(h));
}

// ---------------- transpose + split: W[K,N] -> T[N,K] hi/lo bf16 ----------------
__global__ __launch_bounds__(256)
void transpose_split(const float* __restrict__ W, __nv_bfloat16* __restrict__ Th,
                     __nv_bfloat16* __restrict__ Tl, int K, int N)
{
    __shared__ float t[32][33];
    const int n0 = blockIdx.x * 32, k0 = blockIdx.y * 32;
    const int tx = threadIdx.x & 31, ty = threadIdx.x >> 5;
    #pragma unroll
    for (int i = 0; i < 32; i += 8)
        t[ty + i][tx] = W[(size_t)(k0 + ty + i) * N + n0 + tx];
    __syncthreads();
    #pragma unroll
    for (int i = 0; i < 32; i += 8) {
        float v = t[tx][ty + i];
        __nv_bfloat16 h = __float2bfloat16(v);
        size_t o = (size_t)(n0 + ty + i) * K + k0 + tx;
        Th[o] = h;
        Tl[o] = __float2bfloat16(v - __bfloat162float(h));
    }
}

// ---------------- split QKV + RoPE (fp32) + head transpose ----------------
__global__ __launch_bounds__(256)
void split_rope(const float* __restrict__ xp,
                float* __restrict__ Q, float* __restrict__ K, float* __restrict__ V)
{
    int idx = blockIdx.x * 256 + threadIdx.x;
    int col = idx & (DMODEL - 1);
    int bs  = idx >> 10;
    int h = col >> 6;
    int d = col & (HD - 1);
    int s = bs & (SEQ - 1);
    int b = bs >> 11;

    const float* base = xp + (size_t)bs * (3 * DMODEL);
    float qv, kv;
    if (d < 32) {
        int i = d >> 1;
        float invf = exp2f(-13.287712379549449f * ((float)(2 * i) * (1.0f / 32.0f)));
        float ang = (float)s * invf;
        float sn, c;
        sincosf(ang, &sn, &c);
        float q0 = base[col],          q1 = base[col ^ 1];
        float k0 = base[DMODEL + col], k1 = base[DMODEL + (col ^ 1)];
        if (d & 1) { qv = q0 * c + q1 * sn; kv = k0 * c + k1 * sn; }
        else       { qv = q0 * c - q1 * sn; kv = k0 * c - k1 * sn; }
    } else {
        qv = base[col];
        kv = base[DMODEL + col];
    }
    float vv = base[2 * DMODEL + col];

    size_t o = (((size_t)(b * NH + h)) * SEQ + s) * HD + d;
    Q[o] = qv; K[o] = kv; V[o] = vv;
}

// ---------------- flash attention (fp32), cp.async double-buffered K/V ----------------
#define BCK 32
__global__ __launch_bounds__(128)
void attn_kernel(const float* __restrict__ Q, const float* __restrict__ K,
                 const float* __restrict__ V, const float* __restrict__ x,
                 float* __restrict__ y1,
                 __nv_bfloat16* __restrict__ y1h, __nv_bfloat16* __restrict__ y1l)
{
    __shared__ float Ks[2][BCK][HD];
    __shared__ float Vs[2][BCK][HD];

    const int bh = blockIdx.y;
    const int q0 = blockIdx.x * 128;
    const int t  = threadIdx.x;

    const float* Qb = Q + (size_t)bh * SEQ * HD;
    const float* Kb = K + (size_t)bh * SEQ * HD;
    const float* Vb = V + (size_t)bh * SEQ * HD;

    const int pr_r  = t >> 4;
    const int pr_c4 = t & 15;
    auto prefetch = [&](int kt, int s) {
        #pragma unroll
        for (int p = 0; p < 4; p++) {
            int r = pr_r + p * 8;
            unsigned dk = smem_u32(&Ks[s][r][pr_c4 * 4]);
            unsigned dv = smem_u32(&Vs[s][r][pr_c4 * 4]);
            cp_async16(dk, &Kb[(size_t)(kt + r) * HD + pr_c4 * 4]);
            cp_async16(dv, &Vb[(size_t)(kt + r) * HD + pr_c4 * 4]);
        }
    };

    float q[HD];
    {
        const float* qr = Qb + (size_t)(q0 + t) * HD;
        #pragma unroll
        for (int d4 = 0; d4 < 16; d4++) {
            float4 v4 = *(const float4*)&qr[d4 * 4];
            q[d4 * 4 + 0] = v4.x * (SCALE * LOG2E);
            q[d4 * 4 + 1] = v4.y * (SCALE * LOG2E);
            q[d4 * 4 + 2] = v4.z * (SCALE * LOG2E);
            q[d4 * 4 + 3] = v4.w * (SCALE * LOG2E);
        }
    }

    float acc[HD];
    #pragma unroll
    for (int d = 0; d < HD; d++) acc[d] = 0.f;
    float m = -1e30f, l = 0.f;

    prefetch(0, 0);
    cp_commit();

    int buf = 0;
    for (int kt = 0; kt < SEQ; kt += BCK) {
        if (kt + BCK < SEQ) prefetch(kt + BCK, buf ^ 1);
        cp_commit();
        cp_wait<1>();
        __syncthreads();

        float sc[BCK];
        float mt = m;
        #pragma unroll
        for (int j = 0; j < BCK; j++) {
            float s = 0.f;
            #pragma unroll
            for (int d4 = 0; d4 < 16; d4++) {
                float4 k4 = *(const float4*)&Ks[buf][j][d4 * 4];
                s += q[d4 * 4 + 0] * k4.x;
                s += q[d4 * 4 + 1] * k4.y;
                s += q[d4 * 4 + 2] * k4.z;
                s += q[d4 * 4 + 3] * k4.w;
            }
            sc[j] = s;
            mt = fmaxf(mt, s);
        }

        float corr = exp2f(m - mt);
        m = mt;
        l *= corr;
        #pragma unroll
        for (int d = 0; d < HD; d++) acc[d] *= corr;

        #pragma unroll
        for (int j = 0; j < BCK; j++) {
            float p = exp2f(sc[j] - m);
            l += p;
            #pragma unroll
            for (int d4 = 0; d4 < 16; d4++) {
                float4 v4 = *(const float4*)&Vs[buf][j][d4 * 4];
                acc[d4 * 4 + 0] += p * v4.x;
                acc[d4 * 4 + 1] += p * v4.y;
                acc[d4 * 4 + 2] += p * v4.z;
                acc[d4 * 4 + 3] += p * v4.w;
            }
        }

        __syncthreads();
        buf ^= 1;
    }

    const int b = bh / NH, h = bh % NH;
    const size_t row = (size_t)b * SEQ + q0 + t;
    const size_t off = row * DMODEL + h * HD;
    const float* xr = x + off;
    const float inv_l = 1.f / l;
    #pragma unroll
    for (int d4 = 0; d4 < 16; d4++) {
        float4 xv = *(const float4*)&xr[d4 * 4];
        float4 o;
        o.x = acc[d4 * 4 + 0] * inv_l + xv.x;
        o.y = acc[d4 * 4 + 1] * inv_l + xv.y;
        o.z = acc[d4 * 4 + 2] * inv_l + xv.z;
        o.w = acc[d4 * 4 + 3] * inv_l + xv.w;
        *(float4*)&y1[off + d4 * 4] = o;
        #pragma unroll
        for (int e = 0; e < 4; e++) {
            float v = (&o.x)[e];
            __nv_bfloat16 hh = __float2bfloat16(v);
            y1h[off + d4 * 4 + e] = hh;
            y1l[off + d4 * 4 + e] = __float2bfloat16(v - __bfloat162float(hh));
        }
    }
}

// ---------------- LayerNorm ----------------
__inline__ __device__ float warpsum(float v) {
    #pragma unroll
    for (int o = 16; o; o >>= 1) v += __shfl_xor_sync(0xffffffffu, v, o);
    return v;
}

__global__ __launch_bounds__(256)
void ln_kernel(const float* __restrict__ Y, const float* __restrict__ gamma,
               const float* __restrict__ beta, float* __restrict__ out)
{
    const int row = blockIdx.x;
    const int t = threadIdx.x;
    const float* yr = Y + (size_t)row * DMODEL;

    float vals[4];
    float s = 0.f, s2 = 0.f;
    #pragma unroll
    for (int k = 0; k < 4; k++) {
        float v = yr[t + k * 256];
        vals[k] = v;
        s += v; s2 += v * v;
    }
    s = warpsum(s); s2 = warpsum(s2);

    __shared__ float sh[16];
    int w = t >> 5, ln = t & 31;
    if (ln == 0) { sh[w] = s; sh[8 + w] = s2; }
    __syncthreads();
    if (t == 0) {
        float a = 0.f, a2 = 0.f;
        #pragma unroll
        for (int i = 0; i < 8; i++) { a += sh[i]; a2 += sh[8 + i]; }
        sh[0] = a; sh[8] = a2;
    }
    __syncthreads();
    const float mu  = sh[0] * (1.f / DMODEL);
    const float var = sh[8] * (1.f / DMODEL) - mu * mu;
    const float inv = rsqrtf(var + 1e-5f);

    #pragma unroll
    for (int k = 0; k < 4; k++) {
        int c = t + k * 256;
        out[(size_t)row * DMODEL + c] = (vals[k] - mu) * inv * gamma[c] + beta[c];
    }
}

// ---------------- launch ----------------
extern "C" void kernel_launch(void* const* d_in, const int* in_sizes, int n_in,
                              void* d_out, int out_size)
{
    const float* x      = (const float*)d_in[0];
    const float* w_qkv  = (const float*)d_in[1];
    const float* b_qkv  = (const float*)d_in[2];
    const float* w_out  = (const float*)d_in[3];
    const float* b_out  = (const float*)d_in[4];
    const float* gammap = (const float*)d_in[5];
    const float* betap  = (const float*)d_in[6];
    float* out = (float*)d_out;

    float *xp, *Q, *K, *V, *y1, *y2;
    __nv_bfloat16 *xh, *xl, *wqh, *wql, *woh, *wol, *y1h, *y1l;
    cudaGetSymbolAddress((void**)&xp, g_xp);
    cudaGetSymbolAddress((void**)&Q,  g_q);
    cudaGetSymbolAddress((void**)&K,  g_k);
    cudaGetSymbolAddress((void**)&V,  g_v);
    cudaGetSymbolAddress((void**)&y1, g_y1);
    cudaGetSymbolAddress((void**)&y2, g_y2);
    cudaGetSymbolAddress((void**)&xh, g_xh);
    cudaGetSymbolAddress((void**)&xl, g_xl);
    cudaGetSymbolAddress((void**)&wqh, g_wqh);
    cudaGetSymbolAddress((void**)&wql, g_wql);
    cudaGetSymbolAddress((void**)&woh, g_woh);
    cudaGetSymbolAddress((void**)&wol, g_wol);
    cudaGetSymbolAddress((void**)&y1h, g_y1h);
    cudaGetSymbolAddress((void**)&y1l, g_y1l);

    cudaFuncSetAttribute(gemm_mma, cudaFuncAttributeMaxDynamicSharedMemorySize, 2 * STG);

    // operand prep
    split_x<<<(ROWS * DMODEL) / 256, 256>>>(x, xh, xl);
    transpose_split<<<dim3(3 * DMODEL / 32, DMODEL / 32), 256>>>(w_qkv, wqh, wql, DMODEL, 3 * DMODEL);
    transpose_split<<<dim3(DMODEL / 32, DMODEL / 32), 256>>>(w_out, woh, wol, DMODEL, DMODEL);

    // 1. QKV projection (HMMA): [4096,1024] x [3072,1024]^T
    gemm_mma<<<dim3(3 * DMODEL / 128, ROWS / 128), 256, 2 * STG>>>(
        xh, xl, wqh, wql, b_qkv, xp, 3 * DMODEL, DMODEL);

    // 2. split + RoPE
    split_rope<<<(ROWS * DMODEL) / 256, 256>>>(xp, Q, K, V);

    // 3. attention + residual (+ bf16 split of y1)
    dim3 ga(SEQ / 128, Bsz * NH);
    attn_kernel<<<ga, 128>>>(Q, K, V, x, y1, y1h, y1l);

    // 4. output projection (HMMA): [4096,1024] x [1024,1024]^T
    gemm_mma<<<dim3(DMODEL / 128, ROWS / 128), 256, 2 * STG>>>(
        y1h, y1l, woh, wol, b_out, y2, DMODEL, DMODEL);

    // 5. layernorm
    ln_kernel<<<ROWS, 256>>>(y2, gammap, betap, out);
}

// round 11
// speedup vs baseline: 4.1207x; 2.7772x over previous
#include <cuda_runtime.h>
#include <cuda_bf16.h>
#include <math.h>
#include <stdint.h>

// Problem constants
#define Bsz   2
#define SEQ   2048
#define DMODEL 1024
#define NH    16
#define HD    64
#define ROWS  (Bsz*SEQ)          // 4096
#define SCALE 0.03125f
#define LOG2E 1.4426950408889634f
#define SS (SCALE * LOG2E)

// ---------------- scratch (128B aligned: cp.async.16 needs 16B-aligned global srcs) ----------------
__device__ __align__(128) float g_xp[(size_t)ROWS * 3 * DMODEL];
__device__ __align__(128) float g_y2[(size_t)ROWS * DMODEL];
__device__ __align__(128) __nv_bfloat16 g_xh [(size_t)ROWS * DMODEL];
__device__ __align__(128) __nv_bfloat16 g_xl [(size_t)ROWS * DMODEL];
__device__ __align__(128) __nv_bfloat16 g_wqh[(size_t)3 * DMODEL * DMODEL];
__device__ __align__(128) __nv_bfloat16 g_wql[(size_t)3 * DMODEL * DMODEL];
__device__ __align__(128) __nv_bfloat16 g_woh[(size_t)DMODEL * DMODEL];
__device__ __align__(128) __nv_bfloat16 g_wol[(size_t)DMODEL * DMODEL];
__device__ __align__(128) __nv_bfloat16 g_y1h[(size_t)ROWS * DMODEL];
__device__ __align__(128) __nv_bfloat16 g_y1l[(size_t)ROWS * DMODEL];
__device__ __align__(128) __nv_bfloat16 g_qb[(size_t)Bsz * NH * SEQ * HD];
__device__ __align__(128) __nv_bfloat16 g_kb[(size_t)Bsz * NH * SEQ * HD];
__device__ __align__(128) __nv_bfloat16 g_vt[(size_t)Bsz * NH * HD * SEQ];  // V^T [bh][d][s]

// ---------------- helpers ----------------
__device__ __forceinline__ unsigned smem_u32(const void* p) {
    unsigned a;
    asm("{ .reg .u64 t; cvta.to.shared.u64 t, %1; cvt.u32.u64 %0, t; }" : "=r"(a) : "l"(p));
    return a;
}
__device__ __forceinline__ void cp_async16(unsigned dst, const void* src) {
    asm volatile("cp.async.cg.shared.global [%0], [%1], 16;\n" :: "r"(dst), "l"(src));
}
__device__ __forceinline__ void cp_commit() { asm volatile("cp.async.commit_group;\n"); }
template<int N> __device__ __forceinline__ void cp_wait() {
    asm volatile("cp.async.wait_group %0;\n" :: "n"(N));
}
__device__ __forceinline__ float ex2(float x) {
    float r;
    asm("ex2.approx.ftz.f32 %0, %1;" : "=f"(r) : "f"(x));
    return r;
}
__device__ __forceinline__ void mma_bf16(float* c, unsigned a0, unsigned a1, unsigned a2, unsigned a3,
                                         unsigned b0, unsigned b1) {
    asm volatile(
        "mma.sync.aligned.m16n8k16.row.col.f32.bf16.bf16.f32 "
        "{%0,%1,%2,%3}, {%4,%5,%6,%7}, {%8,%9}, {%0,%1,%2,%3};"
        : "+f"(c[0]), "+f"(c[1]), "+f"(c[2]), "+f"(c[3])
        : "r"(a0), "r"(a1), "r"(a2), "r"(a3), "r"(b0), "r"(b1));
}
__device__ __forceinline__ unsigned pack_bf16(float lo, float hi) {
    __nv_bfloat162 t = __floats2bfloat162_rn(lo, hi);
    return *(unsigned*)&t;
}
__device__ __forceinline__ unsigned pack_raw2(const __nv_bfloat16* p) {
    unsigned short a = *(const unsigned short*)p;
    unsigned short b = *(const unsigned short*)(p + 1);
    return (unsigned)a | ((unsigned)b << 16);
}

// ---------------- HMMA split-bf16 GEMM (proven in R5) ----------------
#define GP 80
#define T_A_H 0
#define T_A_L 10240
#define T_B_H 20480
#define T_B_L 30720
#define STG   40960

__global__ __launch_bounds__(256, 1)
void gemm_mma(const __nv_bfloat16* __restrict__ Ah, const __nv_bfloat16* __restrict__ Al,
              const __nv_bfloat16* __restrict__ Bh, const __nv_bfloat16* __restrict__ Bl,
              const float* __restrict__ bias, float* __restrict__ C,
              int N, int K)
{
    extern __shared__ char dsm[];
    const int tid = threadIdx.x;
    const int wid = tid >> 5;
    const int lid = tid & 31;
    const int wm = wid & 3;
    const int wn = wid >> 2;
    const int bm = blockIdx.y * 128;
    const int bn = blockIdx.x * 128;
    const int gq = lid >> 2;
    const int gr = lid & 3;

    float acc[2][8][4];
    #pragma unroll
    for (int mi = 0; mi < 2; mi++)
        #pragma unroll
        for (int ni = 0; ni < 8; ni++)
            #pragma unroll
            for (int e = 0; e < 4; e++) acc[mi][ni][e] = 0.f;

    const int KITER = K / 32;

    auto prefetch = [&](int it, int s) {
        const int kt = it * 32;
        char* base = dsm + s * STG;
        #pragma unroll
        for (int p = 0; p < 2; p++) {
            int idx = p * 256 + tid;
            int r = idx >> 2, c = idx & 3;
            unsigned dst = smem_u32(base + r * GP + c * 16);
            const size_t ga = (size_t)(bm + r) * K + kt + c * 8;
            const size_t gb = (size_t)(bn + r) * K + kt + c * 8;
            cp_async16(dst + T_A_H, Ah + ga);
            cp_async16(dst + T_A_L, Al + ga);
            cp_async16(dst + T_B_H, Bh + gb);
            cp_async16(dst + T_B_L, Bl + gb);
        }
    };

    prefetch(0, 0); cp_commit();

    int buf = 0;
    for (int i = 0; i < KITER; i++) {
        if (i + 1 < KITER) prefetch(i + 1, buf ^ 1);
        cp_commit();
        cp_wait<1>();
        __syncthreads();

        const char* sA = dsm + buf * STG;
        const char* sB = sA + T_B_H;

        #pragma unroll
        for (int ks = 0; ks < 2; ks++) {
            const int kc2 = (ks * 16 + gr * 2) * 2;
            unsigned aH[2][4], aL[2][4];
            #pragma unroll
            for (int mi = 0; mi < 2; mi++) {
                const int r0 = wm * 32 + mi * 16 + gq;
                const char* pH = sA + T_A_H + kc2;
                const char* pL = sA + T_A_L + kc2;
                aH[mi][0] = *(const unsigned*)(pH + r0 * GP);
                aH[mi][1] = *(const unsigned*)(pH + (r0 + 8) * GP);
                aH[mi][2] = *(const unsigned*)(pH + r0 * GP + 16);
                aH[mi][3] = *(const unsigned*)(pH + (r0 + 8) * GP + 16);
                aL[mi][0] = *(const unsigned*)(pL + r0 * GP);
                aL[mi][1] = *(const unsigned*)(pL + (r0 + 8) * GP);
                aL[mi][2] = *(const unsigned*)(pL + r0 * GP + 16);
                aL[mi][3] = *(const unsigned*)(pL + (r0 + 8) * GP + 16);
            }
            #pragma unroll
            for (int ni = 0; ni < 8; ni++) {
                const int n0 = wn * 64 + ni * 8 + gq;
                unsigned b0h = *(const unsigned*)(sB + n0 * GP + kc2);
                unsigned b1h = *(const unsigned*)(sB + n0 * GP + kc2 + 16);
                unsigned b0l = *(const unsigned*)(sB + 10240 + n0 * GP + kc2);
                unsigned b1l = *(const unsigned*)(sB + 10240 + n0 * GP + kc2 + 16);
                #pragma unroll
                for (int mi = 0; mi < 2; mi++) {
                    mma_bf16(acc[mi][ni], aH[mi][0], aH[mi][1], aH[mi][2], aH[mi][3], b0h, b1h);
                    mma_bf16(acc[mi][ni], aH[mi][0], aH[mi][1], aH[mi][2], aH[mi][3], b0l, b1l);
                    mma_bf16(acc[mi][ni], aL[mi][0], aL[mi][1], aL[mi][2], aL[mi][3], b0h, b1h);
                }
            }
        }
        __syncthreads();
        buf ^= 1;
    }

    #pragma unroll
    for (int mi = 0; mi < 2; mi++) {
        const int row = bm + wm * 32 + mi * 16 + gq;
        #pragma unroll
        for (int ni = 0; ni < 8; ni++) {
            const int col = bn + wn * 64 + ni * 8 + gr * 2;
            C[(size_t)row * N + col]           = acc[mi][ni][0] + bias[col];
            C[(size_t)row * N + col + 1]       = acc[mi][ni][1] + bias[col + 1];
            C[(size_t)(row + 8) * N + col]     = acc[mi][ni][2] + bias[col];
            C[(size_t)(row + 8) * N + col + 1] = acc[mi][ni][3] + bias[col + 1];
        }
    }
}

// ---------------- prep kernels ----------------
__global__ __launch_bounds__(256)
void split_x(const float* __restrict__ X, __nv_bfloat16* __restrict__ Xh,
             __nv_bfloat16* __restrict__ Xl)
{
    int i = blockIdx.x * 256 + threadIdx.x;
    float v = X[i];
    __nv_bfloat16 h = __float2bfloat16(v);
    Xh[i] = h;
    Xl[i] = __float2bfloat16(v - __bfloat162float(h));
}

__global__ __launch_bounds__(256)
void transpose_split(const float* __restrict__ W, __nv_bfloat16* __restrict__ Th,
                     __nv_bfloat16* __restrict__ Tl, int K, int N)
{
    __shared__ float t[32][33];
    const int n0 = blockIdx.x * 32, k0 = blockIdx.y * 32;
    const int tx = threadIdx.x & 31, ty = threadIdx.x >> 5;
    #pragma unroll
    for (int i = 0; i < 32; i += 8)
        t[ty + i][tx] = W[(size_t)(k0 + ty + i) * N + n0 + tx];
    __syncthreads();
    #pragma unroll
    for (int i = 0; i < 32; i += 8) {
        float v = t[tx][ty + i];
        __nv_bfloat16 h = __float2bfloat16(v);
        size_t o = (size_t)(n0 + ty + i) * K + k0 + tx;
        Th[o] = h;
        Tl[o] = __float2bfloat16(v - __bfloat162float(h));
    }
}

// ---------------- split QKV + RoPE -> bf16 Q, K, V^T ----------------
__global__ __launch_bounds__(256)
void split_rope(const float* __restrict__ xp,
                __nv_bfloat16* __restrict__ Qb, __nv_bfloat16* __restrict__ Kb,
                __nv_bfloat16* __restrict__ Vt)
{
    int idx = blockIdx.x * 256 + threadIdx.x;
    int col = idx & (DMODEL - 1);
    int bs  = idx >> 10;
    int h = col >> 6;
    int d = col & (HD - 1);
    int s = bs & (SEQ - 1);
    int b = bs >> 11;

    const float* base = xp + (size_t)bs * (3 * DMODEL);
    float qv, kv;
    if (d < 32) {
        int i = d >> 1;
        float invf = exp2f(-13.287712379549449f * ((float)(2 * i) * (1.0f / 32.0f)));
        float ang = (float)s * invf;
        float sn, c;
        sincosf(ang, &sn, &c);
        float q0 = base[col],          q1 = base[col ^ 1];
        float k0 = base[DMODEL + col], k1 = base[DMODEL + (col ^ 1)];
        if (d & 1) { qv = q0 * c + q1 * sn; kv = k0 * c + k1 * sn; }
        else       { qv = q0 * c - q1 * sn; kv = k0 * c - k1 * sn; }
    } else {
        qv = base[col];
        kv = base[DMODEL + col];
    }
    float vv = base[2 * DMODEL + col];

    const int bh = b * NH + h;
    size_t o = ((size_t)bh * SEQ + s) * HD + d;
    Qb[o] = __float2bfloat16(qv);
    Kb[o] = __float2bfloat16(kv);
    Vt[((size_t)bh * HD + d) * SEQ + s] = __float2bfloat16(vv);
}

// ---------------- HMMA flash attention ----------------
#define KP 144                     // smem row pitch bytes (128B data + 16B pad)
#define ATILE (64 * KP)
#define ASTG (2 * ATILE)

__global__ __launch_bounds__(256, 1)
void attn_mma(const __nv_bfloat16* __restrict__ Qb, const __nv_bfloat16* __restrict__ Kb,
              const __nv_bfloat16* __restrict__ Vt, const float* __restrict__ x,
              __nv_bfloat16* __restrict__ y1h, __nv_bfloat16* __restrict__ y1l)
{
    extern __shared__ char dsm[];

    const int bh = blockIdx.y;
    const int q0 = blockIdx.x * 128;
    const int tid = threadIdx.x;
    const int wid = tid >> 5;
    const int lid = tid & 31;
    const int gq = lid >> 2;
    const int gr = lid & 3;

    const __nv_bfloat16* Kbase = Kb + (size_t)bh * SEQ * HD;
    const __nv_bfloat16* Vbase = Vt + (size_t)bh * HD * SEQ;

    // takes TILE INDEX it; key offset kt = it * 64  (the R6-R10 fault: callers
    // passed tile index into a key-offset parameter -> odd 2B global offsets in
    // the V^T branch -> misaligned cp.async.16)
    auto prefetch = [&](int it, int s) {
        const int kt = it * 64;
        char* base = dsm + s * ASTG;
        #pragma unroll
        for (int p = 0; p < 4; p++) {
            int idx = p * 256 + tid;       // 0..1023
            if (idx < 512) {               // K: row r, chunk c
                int r = idx >> 3, c = idx & 7;
                cp_async16(smem_u32(base + r * KP + c * 16),
                           Kbase + (size_t)(kt + r) * HD + c * 8);
            } else {
                int i2 = idx - 512;        // V^T: row d, chunk c
                int d = i2 >> 3, c = i2 & 7;
                cp_async16(smem_u32(base + ATILE + d * KP + c * 16),
                           Vbase + (size_t)d * SEQ + kt + c * 8);
            }
        }
    };

    // Q fragments via 2-byte loads
    unsigned qa[4][4];
    {
        const __nv_bfloat16* Qr  = Qb + ((size_t)bh * SEQ + q0 + wid * 16 + gq) * HD;
        const __nv_bfloat16* Qr8 = Qr + 8 * HD;
        #pragma unroll
        for (int ks = 0; ks < 4; ks++) {
            const int k0 = ks * 16 + gr * 2;
            qa[ks][0] = pack_raw2(Qr  + k0);
            qa[ks][1] = pack_raw2(Qr8 + k0);
            qa[ks][2] = pack_raw2(Qr  + k0 + 8);
            qa[ks][3] = pack_raw2(Qr8 + k0 + 8);
        }
    }

    float ao[8][4];
    #pragma unroll
    for (int nd = 0; nd < 8; nd++)
        #pragma unroll
        for (int e = 0; e < 4; e++) ao[nd][e] = 0.f;
    float m0 = -1e30f, m1 = -1e30f, l0 = 0.f, l1 = 0.f;

    prefetch(0, 0); cp_commit();

    int buf = 0;
    for (int t = 0; t < SEQ / 64; t++) {
        if (t + 1 < SEQ / 64) prefetch(t + 1, buf ^ 1);
        cp_commit();
        cp_wait<1>();
        __syncthreads();

        const char* sK = dsm + buf * ASTG;
        const char* sV = sK + ATILE;

        // S = Q K^T
        float sc[8][4];
        #pragma unroll
        for (int ni = 0; ni < 8; ni++)
            #pragma unroll
            for (int e = 0; e < 4; e++) sc[ni][e] = 0.f;

        #pragma unroll
        for (int ks = 0; ks < 4; ks++) {
            const int kc = ks * 32 + gr * 4;
            #pragma unroll
            for (int ni = 0; ni < 8; ni++) {
                const char* pb = sK + (ni * 8 + gq) * KP + kc;
                unsigned b0 = *(const unsigned*)pb;
                unsigned b1 = *(const unsigned*)(pb + 16);
                mma_bf16(sc[ni], qa[ks][0], qa[ks][1], qa[ks][2], qa[ks][3], b0, b1);
            }
        }

        // online softmax (log2 domain)
        float tm0 = -1e30f, tm1 = -1e30f;
        #pragma unroll
        for (int ni = 0; ni < 8; ni++) {
            tm0 = fmaxf(tm0, fmaxf(sc[ni][0], sc[ni][1]));
            tm1 = fmaxf(tm1, fmaxf(sc[ni][2], sc[ni][3]));
        }
        tm0 *= SS; tm1 *= SS;
        tm0 = fmaxf(tm0, __shfl_xor_sync(0xffffffffu, tm0, 1));
        tm0 = fmaxf(tm0, __shfl_xor_sync(0xffffffffu, tm0, 2));
        tm1 = fmaxf(tm1, __shfl_xor_sync(0xffffffffu, tm1, 1));
        tm1 = fmaxf(tm1, __shfl_xor_sync(0xffffffffu, tm1, 2));

        float m0n = fmaxf(m0, tm0), m1n = fmaxf(m1, tm1);
        float c0 = ex2(m0 - m0n), c1 = ex2(m1 - m1n);
        m0 = m0n; m1 = m1n;
        l0 *= c0; l1 *= c1;
        #pragma unroll
        for (int nd = 0; nd < 8; nd++) {
            ao[nd][0] *= c0; ao[nd][1] *= c0;
            ao[nd][2] *= c1; ao[nd][3] *= c1;
        }

        #pragma unroll
        for (int ni = 0; ni < 8; ni++) {
            sc[ni][0] = ex2(sc[ni][0] * SS - m0);
            sc[ni][1] = ex2(sc[ni][1] * SS - m0);
            sc[ni][2] = ex2(sc[ni][2] * SS - m1);
            sc[ni][3] = ex2(sc[ni][3] * SS - m1);
            l0 += sc[ni][0] + sc[ni][1];
            l1 += sc[ni][2] + sc[ni][3];
        }

        // pack P to bf16 A-fragments
        unsigned pa[4][4];
        #pragma unroll
        for (int ki = 0; ki < 4; ki++) {
            pa[ki][0] = pack_bf16(sc[2 * ki][0],     sc[2 * ki][1]);
            pa[ki][1] = pack_bf16(sc[2 * ki][2],     sc[2 * ki][3]);
            pa[ki][2] = pack_bf16(sc[2 * ki + 1][0], sc[2 * ki + 1][1]);
            pa[ki][3] = pack_bf16(sc[2 * ki + 1][2], sc[2 * ki + 1][3]);
        }

        // O += P V
        #pragma unroll
        for (int ki = 0; ki < 4; ki++) {
            const int kc = ki * 32 + gr * 4;
            #pragma unroll
            for (int nd = 0; nd < 8; nd++) {
                const char* pb = sV + (nd * 8 + gq) * KP + kc;
                unsigned b0 = *(const unsigned*)pb;
                unsigned b1 = *(const unsigned*)(pb + 16);
                mma_bf16(ao[nd], pa[ki][0], pa[ki][1], pa[ki][2], pa[ki][3], b0, b1);
            }
        }

        __syncthreads();
        buf ^= 1;
    }

    // final row sums
    l0 += __shfl_xor_sync(0xffffffffu, l0, 1);
    l0 += __shfl_xor_sync(0xffffffffu, l0, 2);
    l1 += __shfl_xor_sync(0xffffffffu, l1, 1);
    l1 += __shfl_xor_sync(0xffffffffu, l1, 2);
    const float inv0 = 1.f / l0, inv1 = 1.f / l1;

    const int b = bh / NH, h = bh % NH;
    const int r0 = q0 + wid * 16 + gq;
    const size_t off0 = ((size_t)b * SEQ + r0) * DMODEL + h * HD;
    const size_t off1 = off0 + 8 * DMODEL;

    #pragma unroll
    for (int nd = 0; nd < 8; nd++) {
        const int col = nd * 8 + gr * 2;
        #pragma unroll
        for (int e = 0; e < 2; e++) {
            float v0 = ao[nd][e]     * inv0 + x[off0 + col + e];
            float v1 = ao[nd][2 + e] * inv1 + x[off1 + col + e];
            __nv_bfloat16 h0 = __float2bfloat16(v0);
            __nv_bfloat16 h1 = __float2bfloat16(v1);
            y1h[off0 + col + e] = h0;
            y1h[off1 + col + e] = h1;
            y1l[off0 + col + e] = __float2bfloat16(v0 - __bfloat162float(h0));
            y1l[off1 + col + e] = __float2bfloat16(v1 - __bfloat162float(h1));
        }
    }
}

// ---------------- LayerNorm ----------------
__inline__ __device__ float warpsum(float v) {
    #pragma unroll
    for (int o = 16; o; o >>= 1) v += __shfl_xor_sync(0xffffffffu, v, o);
    return v;
}

__global__ __launch_bounds__(256)
void ln_kernel(const float* __restrict__ Y, const float* __restrict__ gamma,
               const float* __restrict__ beta, float* __restrict__ out)
{
    const int row = blockIdx.x;
    const int t = threadIdx.x;
    const float* yr = Y + (size_t)row * DMODEL;

    float vals[4];
    float s = 0.f, s2 = 0.f;
    #pragma unroll
    for (int k = 0; k < 4; k++) {
        float v = yr[t + k * 256];
        vals[k] = v;
        s += v; s2 += v * v;
    }
    s = warpsum(s); s2 = warpsum(s2);

    __shared__ float sh[16];
    int w = t >> 5, ln = t & 31;
    if (ln == 0) { sh[w] = s; sh[8 + w] = s2; }
    __syncthreads();
    if (t == 0) {
        float a = 0.f, a2 = 0.f;
        #pragma unroll
        for (int i = 0; i < 8; i++) { a += sh[i]; a2 += sh[8 + i]; }
        sh[0] = a; sh[8] = a2;
    }
    __syncthreads();
    const float mu  = sh[0] * (1.f / DMODEL);
    const float var = sh[8] * (1.f / DMODEL) - mu * mu;
    const float inv = rsqrtf(var + 1e-5f);

    #pragma unroll
    for (int k = 0; k < 4; k++) {
        int c = t + k * 256;
        out[(size_t)row * DMODEL + c] = (vals[k] - mu) * inv * gamma[c] + beta[c];
    }
}

// ---------------- launch ----------------
extern "C" void kernel_launch(void* const* d_in, const int* in_sizes, int n_in,
                              void* d_out, int out_size)
{
    const float* x      = (const float*)d_in[0];
    const float* w_qkv  = (const float*)d_in[1];
    const float* b_qkv  = (const float*)d_in[2];
    const float* w_out  = (const float*)d_in[3];
    const float* b_out  = (const float*)d_in[4];
    const float* gammap = (const float*)d_in[5];
    const float* betap  = (const float*)d_in[6];
    float* out = (float*)d_out;

    float *xp, *y2;
    __nv_bfloat16 *xh, *xl, *wqh, *wql, *woh, *wol, *y1h, *y1l, *qb, *kb, *vt;
    cudaGetSymbolAddress((void**)&xp, g_xp);
    cudaGetSymbolAddress((void**)&y2, g_y2);
    cudaGetSymbolAddress((void**)&xh, g_xh);
    cudaGetSymbolAddress((void**)&xl, g_xl);
    cudaGetSymbolAddress((void**)&wqh, g_wqh);
    cudaGetSymbolAddress((void**)&wql, g_wql);
    cudaGetSymbolAddress((void**)&woh, g_woh);
    cudaGetSymbolAddress((void**)&wol, g_wol);
    cudaGetSymbolAddress((void**)&y1h, g_y1h);
    cudaGetSymbolAddress((void**)&y1l, g_y1l);
    cudaGetSymbolAddress((void**)&qb, g_qb);
    cudaGetSymbolAddress((void**)&kb, g_kb);
    cudaGetSymbolAddress((void**)&vt, g_vt);

    cudaFuncSetAttribute(gemm_mma, cudaFuncAttributeMaxDynamicSharedMemorySize, 2 * STG);
    cudaFuncSetAttribute(attn_mma, cudaFuncAttributeMaxDynamicSharedMemorySize, 2 * ASTG);

    // operand prep
    split_x<<<(ROWS * DMODEL) / 256, 256>>>(x, xh, xl);
    transpose_split<<<dim3(3 * DMODEL / 32, DMODEL / 32), 256>>>(w_qkv, wqh, wql, DMODEL, 3 * DMODEL);
    transpose_split<<<dim3(DMODEL / 32, DMODEL / 32), 256>>>(w_out, woh, wol, DMODEL, DMODEL);

    // 1. QKV projection (HMMA)
    gemm_mma<<<dim3(3 * DMODEL / 128, ROWS / 128), 256, 2 * STG>>>(
        xh, xl, wqh, wql, b_qkv, xp, 3 * DMODEL, DMODEL);

    // 2. split + RoPE -> bf16 Q, K, V^T
    split_rope<<<(ROWS * DMODEL) / 256, 256>>>(xp, qb, kb, vt);

    // 3. HMMA flash attention + residual -> y1 hi/lo
    dim3 ga(SEQ / 128, Bsz * NH);
    attn_mma<<<ga, 256, 2 * ASTG>>>(qb, kb, vt, x, y1h, y1l);

    // 4. output projection (HMMA)
    gemm_mma<<<dim3(DMODEL / 128, ROWS / 128), 256, 2 * STG>>>(
        y1h, y1l, woh, wol, b_out, y2, DMODEL, DMODEL);

    // 5. layernorm
    ln_kernel<<<ROWS, 256>>>(y2, gammap, betap, out);
}